// round 4
// baseline (speedup 1.0000x reference)
#include <cuda_runtime.h>
#include <math.h>

// ROI max pooling, bit-exact vs JAX/XLA reference (contract proven in R2):
//   coords * 0.0625f -> __float2int_rn (round-half-even)
//   bin = roi_size * RN(1/7)   (XLA folds /7 into *recip)
//   floor/ceil edges, clip [0,50], empty bin -> 0.
//
// R4 structure:
//   K1: transpose x (B,256,2500) -> scr (B,2500,256)  [channels-last scratch]
//   K2: block = ROI, thread = channel. All lanes share bin bounds (zero
//       divergence); every gather load is one coalesced 128B line. Results
//       staged in smem in output layout, then float4 linear copy out.

static constexpr int   kC    = 256;
static constexpr int   kH    = 50;
static constexpr int   kW    = 50;
static constexpr int   kHW   = kH * kW;        // 2500
static constexpr int   kBins = 49;
static constexpr float kScale = 0.0625f;

__device__ float g_scr[4 * kHW * kC];          // 10.24 MB channels-last scratch

// ---------------- K1: NCHW -> NHWC transpose (per batch: 256 x 2500 -> 2500 x 256)
__global__ void __launch_bounds__(256)
transpose_kernel(const float* __restrict__ x)
{
    __shared__ float tile[32][33];
    const int b   = blockIdx.z;
    const int hw0 = blockIdx.x * 32;
    const int c0  = blockIdx.y * 32;
    const int tx  = threadIdx.x;               // 32
    const int ty  = threadIdx.y;               // 8

    const float* src = x + ((size_t)b * kC + c0) * kHW + hw0;
    #pragma unroll
    for (int k = 0; k < 4; ++k) {
        int hw = hw0 + tx;
        if (hw < kHW)
            tile[ty + k * 8][tx] = src[(ty + k * 8) * kHW + tx];
    }
    __syncthreads();

    float* dst = g_scr + ((size_t)b * kHW + hw0) * kC + c0;
    #pragma unroll
    for (int k = 0; k < 4; ++k) {
        int hw = hw0 + ty + k * 8;
        if (hw < kHW)
            dst[(ty + k * 8) * kC + tx] = tile[tx][ty + k * 8];
    }
}

// ---------------- K2: pooling from channels-last scratch
__global__ void __launch_bounds__(256, 4)
roi_pool_nhwc(const float* __restrict__ rois,
              float* __restrict__ out)
{
    extern __shared__ float sout[];            // kC * 49 floats = 50176 B

    const int m = blockIdx.x;
    const int c = threadIdx.x;                 // channel

    const float* r = rois + (size_t)m * 5;
    const int b  = (int)r[0];
    const int x1 = __float2int_rn(r[1] * kScale);
    const int y1 = __float2int_rn(r[2] * kScale);
    const int x2 = __float2int_rn(r[3] * kScale);
    const int y2 = __float2int_rn(r[4] * kScale);

    const float roi_h = (float)max(y2 - y1 + 1, 1);
    const float roi_w = (float)max(x2 - x1 + 1, 1);
    const float kInv7 = 1.0f / 7.0f;           // RN(1/7), matches XLA
    const float bh = roi_h * kInv7;
    const float bw = roi_w * kInv7;

    int hs[7], he[7], wss[7], wee[7];
    #pragma unroll
    for (int i = 0; i < 7; ++i) {
        hs[i]  = min(max((int)floorf((float)i * bh)      + y1, 0), kH);
        he[i]  = min(max((int)ceilf((float)(i + 1) * bh) + y1, 0), kH);
        wss[i] = min(max((int)floorf((float)i * bw)      + x1, 0), kW);
        wee[i] = min(max((int)ceilf((float)(i + 1) * bw) + x1, 0), kW);
    }

    const float* __restrict__ base = g_scr + (size_t)b * kHW * kC + c;
    float* __restrict__ srow = sout + c * kBins;

    #pragma unroll
    for (int i = 0; i < 7; ++i) {
        const int h0 = hs[i], h1 = he[i];
        #pragma unroll
        for (int j = 0; j < 7; ++j) {
            const int w0 = wss[j], w1 = wee[j];
            float v = -INFINITY;
            for (int h = h0; h < h1; ++h) {
                const float* p = base + (size_t)(h * kW + w0) * kC;
                for (int w = w0; w < w1; ++w) {
                    v = fmaxf(v, *p);
                    p += kC;
                }
            }
            const bool valid = (h1 > h0) && (w1 > w0);
            srow[i * 7 + j] = valid ? v : 0.0f;
        }
    }
    __syncthreads();

    // Linear coalesced copy: smem layout == out slice layout (c*49+bin).
    const float4* __restrict__ s4 = (const float4*)sout;
    float4* __restrict__ o4 = (float4*)(out + (size_t)m * (kC * kBins));
    const int n4 = kC * kBins / 4;             // 3136
    #pragma unroll 4
    for (int k = c; k < n4; k += 256)
        o4[k] = s4[k];
}

extern "C" void kernel_launch(void* const* d_in, const int* in_sizes, int n_in,
                              void* d_out, int out_size)
{
    const float* x    = (const float*)d_in[0];
    const float* rois = (const float*)d_in[1];
    float*       out  = (float*)d_out;

    const int B = in_sizes[0] / (kC * kHW);
    const int M = in_sizes[1] / 5;

    static bool attr_set = false;
    const int smem_bytes = kC * kBins * sizeof(float);   // 50176 > 48K static limit
    if (!attr_set) {   // host-side attribute, idempotent & not a stream op
        cudaFuncSetAttribute(roi_pool_nhwc,
                             cudaFuncAttributeMaxDynamicSharedMemorySize,
                             smem_bytes);
        attr_set = true;
    }

    dim3 tgrid((kHW + 31) / 32, kC / 32, B);   // (79, 8, B)
    transpose_kernel<<<tgrid, dim3(32, 8)>>>(x);

    roi_pool_nhwc<<<M, kC, smem_bytes>>>(rois, out);
}

// round 5
// speedup vs baseline: 2.7538x; 2.7538x over previous
#include <cuda_runtime.h>
#include <math.h>

// ROI max pooling, bit-exact vs JAX/XLA reference (contract proven in R2):
//   coords * 0.0625f -> __float2int_rn (round-half-even)
//   bin = roi_size * RN(1/7)   (XLA folds /7 into *recip)
//   floor/ceil edges, clip [0,50], empty bin -> 0.
//
// R5 structure:
//   K1: transpose x (B,256,2500) -> g_scr (B,2500,256)  channels-last.
//   K2: grid (M, 8). Block = (roi, 32-channel group). lane = channel
//       (coalesced loads, zero divergence: all lanes share bin bounds);
//       warp = bin worker (49 bins striped over 8 warps). Results staged
//       in smem, written out as contiguous float4.

static constexpr int   kC    = 256;
static constexpr int   kH    = 50;
static constexpr int   kW    = 50;
static constexpr int   kHW   = kH * kW;        // 2500
static constexpr int   kBins = 49;
static constexpr float kScale = 0.0625f;

__device__ float g_scr[4 * kHW * kC];          // 10.24 MB channels-last scratch

// ---------------- K1: NCHW -> NHWC transpose
__global__ void __launch_bounds__(256)
transpose_kernel(const float* __restrict__ x)
{
    __shared__ float tile[32][33];
    const int b   = blockIdx.z;
    const int hw0 = blockIdx.x * 32;
    const int c0  = blockIdx.y * 32;
    const int tx  = threadIdx.x;               // 32
    const int ty  = threadIdx.y;               // 8

    const float* src = x + ((size_t)b * kC + c0) * kHW + hw0;
    #pragma unroll
    for (int k = 0; k < 4; ++k) {
        if (hw0 + tx < kHW)
            tile[ty + k * 8][tx] = src[(ty + k * 8) * kHW + tx];
    }
    __syncthreads();

    float* dst = g_scr + ((size_t)b * kHW + hw0) * kC + c0;
    #pragma unroll
    for (int k = 0; k < 4; ++k) {
        if (hw0 + ty + k * 8 < kHW)
            dst[(ty + k * 8) * kC + tx] = tile[tx][ty + k * 8];
    }
}

// ---------------- K2: pooling from channels-last scratch
__global__ void __launch_bounds__(256, 8)
roi_pool_nhwc(const float* __restrict__ rois,
              float* __restrict__ out)
{
    __shared__ int4 bnds[kBins];               // (hs, he, ws, we) per bin
    __shared__ int  sb;                        // batch index
    __shared__ __align__(16) float sout[32 * kBins];

    const int m    = blockIdx.x;               // ROI
    const int cg   = blockIdx.y;               // channel group 0..7
    const int t    = threadIdx.x;
    const int lane = t & 31;                   // channel within group
    const int wk   = t >> 5;                   // bin worker 0..7

    const float* r = rois + (size_t)m * 5;

    if (t < kBins) {
        const int x1 = __float2int_rn(r[1] * kScale);
        const int y1 = __float2int_rn(r[2] * kScale);
        const int x2 = __float2int_rn(r[3] * kScale);
        const int y2 = __float2int_rn(r[4] * kScale);

        const float roi_h = (float)max(y2 - y1 + 1, 1);
        const float roi_w = (float)max(x2 - x1 + 1, 1);
        const float kInv7 = 1.0f / 7.0f;       // RN(1/7), matches XLA
        const float bh = roi_h * kInv7;
        const float bw = roi_w * kInv7;

        const int ph = t / 7;
        const int pw = t - ph * 7;

        int hs = min(max((int)floorf((float)ph * bh)       + y1, 0), kH);
        int he = min(max((int)ceilf((float)(ph + 1) * bh)  + y1, 0), kH);
        int ws = min(max((int)floorf((float)pw * bw)       + x1, 0), kW);
        int we = min(max((int)ceilf((float)(pw + 1) * bw)  + x1, 0), kW);
        bnds[t] = make_int4(hs, he, ws, we);
        if (t == 0) sb = (int)r[0];
    }
    __syncthreads();

    const int c = cg * 32 + lane;
    const float* __restrict__ base = g_scr + (size_t)sb * kHW * kC + c;

    for (int bin = wk; bin < kBins; bin += 8) {
        const int4 bb = bnds[bin];             // uniform across warp
        float v = -INFINITY;
        for (int h = bb.x; h < bb.y; ++h) {
            const float* __restrict__ p = base + (size_t)(h * kW + bb.z) * kC;
            for (int w = bb.z; w < bb.w; ++w) {
                v = fmaxf(v, __ldg(p));
                p += kC;
            }
        }
        const bool valid = (bb.y > bb.x) && (bb.w > bb.z);
        sout[lane * kBins + bin] = valid ? v : 0.0f;   // stride 49: conflict-free
    }
    __syncthreads();

    // out slice for (m, channels [cg*32, cg*32+32)) is 1568 contiguous floats.
    float4* __restrict__ o4 =
        (float4*)(out + (size_t)m * (kC * kBins) + (size_t)cg * (32 * kBins));
    const float4* __restrict__ s4 = (const float4*)sout;
    #pragma unroll 2
    for (int k = t; k < 32 * kBins / 4; k += 256)      // 392 float4
        o4[k] = s4[k];
}

extern "C" void kernel_launch(void* const* d_in, const int* in_sizes, int n_in,
                              void* d_out, int out_size)
{
    const float* x    = (const float*)d_in[0];
    const float* rois = (const float*)d_in[1];
    float*       out  = (float*)d_out;

    const int B = in_sizes[0] / (kC * kHW);
    const int M = in_sizes[1] / 5;

    dim3 tgrid((kHW + 31) / 32, kC / 32, B);   // (79, 8, B)
    transpose_kernel<<<tgrid, dim3(32, 8)>>>(x);

    dim3 pgrid(M, kC / 32);                    // (M, 8) = 2048 blocks
    roi_pool_nhwc<<<pgrid, 256>>>(rois, out);
}

// round 6
// speedup vs baseline: 3.6904x; 1.3401x over previous
#include <cuda_runtime.h>
#include <math.h>

// ROI max pooling, bit-exact vs JAX/XLA reference (contract proven in R2):
//   coords * 0.0625f -> __float2int_rn (round-half-even)
//   bin = roi_size * RN(1/7)   (XLA folds /7 into *recip)
//   floor/ceil edges, clip [0,50], empty bin -> 0.
//
// R6 structure:
//   K1: transpose x (B,256,2500) -> g_scr (B,2500,256)  channels-last.
//   K2: grid (M, 2), block 512. Block = (roi, 128-channel group).
//       lane = channel quad (float4 load: one LDG.128 serves 128 channels
//       per warp, 4x fewer load instructions than R5). 16 warps stripe the
//       49 bins (~3 each). All lanes share bin bounds -> zero divergence.
//       Stage in smem (c-major), coalesced float4 copy out.

static constexpr int   kC    = 256;
static constexpr int   kH    = 50;
static constexpr int   kW    = 50;
static constexpr int   kHW   = kH * kW;        // 2500
static constexpr int   kBins = 49;
static constexpr float kScale = 0.0625f;

__device__ float g_scr[4 * kHW * kC];          // 10.24 MB channels-last scratch

// ---------------- K1: NCHW -> NHWC transpose
__global__ void __launch_bounds__(256)
transpose_kernel(const float* __restrict__ x)
{
    __shared__ float tile[32][33];
    const int b   = blockIdx.z;
    const int hw0 = blockIdx.x * 32;
    const int c0  = blockIdx.y * 32;
    const int tx  = threadIdx.x;               // 32
    const int ty  = threadIdx.y;               // 8

    const float* src = x + ((size_t)b * kC + c0) * kHW + hw0;
    #pragma unroll
    for (int k = 0; k < 4; ++k) {
        if (hw0 + tx < kHW)
            tile[ty + k * 8][tx] = src[(ty + k * 8) * kHW + tx];
    }
    __syncthreads();

    float* dst = g_scr + ((size_t)b * kHW + hw0) * kC + c0;
    #pragma unroll
    for (int k = 0; k < 4; ++k) {
        if (hw0 + ty + k * 8 < kHW)
            dst[(ty + k * 8) * kC + tx] = tile[tx][ty + k * 8];
    }
}

// ---------------- K2: pooling from channels-last scratch (float4 per lane)
__global__ void __launch_bounds__(512, 2)
roi_pool_nhwc(const float* __restrict__ rois,
              float* __restrict__ out)
{
    __shared__ int4 bnds[kBins];               // (hs, he, ws, we) per bin
    __shared__ int  sb;                        // batch index
    __shared__ __align__(16) float sout[128 * kBins];   // 25088 B

    const int m    = blockIdx.x;               // ROI
    const int cg   = blockIdx.y;               // channel group 0..1 (128 ch)
    const int t    = threadIdx.x;
    const int lane = t & 31;                   // channel quad within group
    const int wk   = t >> 5;                   // bin worker 0..15

    const float* r = rois + (size_t)m * 5;

    if (t < kBins) {
        const int x1 = __float2int_rn(r[1] * kScale);
        const int y1 = __float2int_rn(r[2] * kScale);
        const int x2 = __float2int_rn(r[3] * kScale);
        const int y2 = __float2int_rn(r[4] * kScale);

        const float roi_h = (float)max(y2 - y1 + 1, 1);
        const float roi_w = (float)max(x2 - x1 + 1, 1);
        const float kInv7 = 1.0f / 7.0f;       // RN(1/7), matches XLA
        const float bh = roi_h * kInv7;
        const float bw = roi_w * kInv7;

        const int ph = t / 7;
        const int pw = t - ph * 7;

        int hs = min(max((int)floorf((float)ph * bh)       + y1, 0), kH);
        int he = min(max((int)ceilf((float)(ph + 1) * bh)  + y1, 0), kH);
        int ws = min(max((int)floorf((float)pw * bw)       + x1, 0), kW);
        int we = min(max((int)ceilf((float)(pw + 1) * bw)  + x1, 0), kW);
        bnds[t] = make_int4(hs, he, ws, we);
        if (t == 0) sb = (int)r[0];
    }
    __syncthreads();

    // base in float4 units: lane's quad = channels cg*128 + 4*lane .. +3
    const float4* __restrict__ base4 =
        (const float4*)g_scr + (size_t)sb * (kHW * kC / 4) + cg * 32 + lane;

    for (int bin = wk; bin < kBins; bin += 16) {
        const int4 bb = bnds[bin];             // uniform across warp
        float v0 = -INFINITY, v1 = -INFINITY, v2 = -INFINITY, v3 = -INFINITY;
        for (int h = bb.x; h < bb.y; ++h) {
            const float4* __restrict__ p = base4 + (size_t)(h * kW + bb.z) * 64;
            for (int w = bb.z; w < bb.w; ++w) {
                const float4 f = __ldg(p);
                v0 = fmaxf(v0, f.x);
                v1 = fmaxf(v1, f.y);
                v2 = fmaxf(v2, f.z);
                v3 = fmaxf(v3, f.w);
                p += 64;                       // next (h,w) cell, same quad
            }
        }
        const bool valid = (bb.y > bb.x) && (bb.w > bb.z);
        float* s = sout + (4 * lane) * kBins + bin;    // c-major staging
        s[0 * kBins] = valid ? v0 : 0.0f;
        s[1 * kBins] = valid ? v1 : 0.0f;
        s[2 * kBins] = valid ? v2 : 0.0f;
        s[3 * kBins] = valid ? v3 : 0.0f;
    }
    __syncthreads();

    // out slice for (m, channels [cg*128, cg*128+128)) = 6272 contiguous floats
    float4* __restrict__ o4 =
        (float4*)(out + (size_t)m * (kC * kBins) + (size_t)cg * (128 * kBins));
    const float4* __restrict__ s4 = (const float4*)sout;
    #pragma unroll
    for (int k = t; k < 128 * kBins / 4; k += 512)     // 1568 float4
        o4[k] = s4[k];
}

extern "C" void kernel_launch(void* const* d_in, const int* in_sizes, int n_in,
                              void* d_out, int out_size)
{
    const float* x    = (const float*)d_in[0];
    const float* rois = (const float*)d_in[1];
    float*       out  = (float*)d_out;

    const int B = in_sizes[0] / (kC * kHW);
    const int M = in_sizes[1] / 5;

    dim3 tgrid((kHW + 31) / 32, kC / 32, B);   // (79, 8, B)
    transpose_kernel<<<tgrid, dim3(32, 8)>>>(x);

    dim3 pgrid(M, 2);                          // (M, 2) = 512 blocks x 512 thr
    roi_pool_nhwc<<<pgrid, 512>>>(rois, out);
}